// round 8
// baseline (speedup 1.0000x reference)
#include <cuda_runtime.h>
#include <math_constants.h>

#define NROWS 32768
#define C_ENT 1000
#define C_REL 500
#define ROWS_PER_BLK 2
#define NBLK (NROWS / ROWS_PER_BLK)   // 16384

// per-block partial loss sums (device global: no allocations allowed)
__device__ float g_partial[NBLK];

__device__ __forceinline__ void top2_update(float x, int i, float& m1, float& m2, int& i1) {
    if (x > m1) { m2 = m1; m1 = x; i1 = i; }
    else if (x > m2) { m2 = x; }
}

__global__ void __launch_bounds__(192) rank_rows_kernel(
    const float* __restrict__ sub, const float* __restrict__ rel, const float* __restrict__ obj,
    const int* __restrict__ t_sub, const int* __restrict__ t_rel, const int* __restrict__ t_obj)
{
    const int tid  = threadIdx.x;
    const int lane = tid & 31;
    const int w    = tid >> 5;          // 0..5
    const int rloc = (w >= 3) ? 1 : 0;  // row within block
    const int t    = w - rloc * 3;      // tensor 0/1/2
    const int r    = blockIdx.x * ROWS_PER_BLK + rloc;

    const float* base;
    const int*   tptr;
    int nvec;
    if (t == 0)      { base = sub + (size_t)r * C_ENT; nvec = C_ENT / 4; tptr = t_sub; }
    else if (t == 1) { base = rel + (size_t)r * C_REL; nvec = C_REL / 4; tptr = t_rel; }
    else             { base = obj + (size_t)r * C_ENT; nvec = C_ENT / 4; tptr = t_obj; }

    // issue the target-index load first so the dependent gather starts ASAP
    int tgt = 0;
    if (lane == 0) tgt = tptr[r];

    // ---- issue all vector loads (MLP = 8 per lane) ----
    float4 v[8];
    #pragma unroll
    for (int j = 0; j < 8; ++j) {
        const int idx = j * 32 + lane;
        v[j] = (idx < nvec) ? ((const float4*)base)[idx]
                            : make_float4(-CUDART_INF_F, -CUDART_INF_F, -CUDART_INF_F, -CUDART_INF_F);
    }

    // dependent target-logit gather (lane 0 only); overlaps with reduction below
    float xt = 0.f;
    if (lane == 0) xt = base[tgt];

    // ---- per-lane top-2 with argmax ----
    // every lane has at least one active vector (j=0: lane < 32 <= nvec), so m1 is finite.
    float m1 = -CUDART_INF_F, m2 = -CUDART_INF_F;
    int   i1 = -1;
    #pragma unroll
    for (int j = 0; j < 8; ++j) {
        const int bi = (j * 32 + lane) * 4;
        top2_update(v[j].x, bi + 0, m1, m2, i1);
        top2_update(v[j].y, bi + 1, m1, m2, i1);
        top2_update(v[j].z, bi + 2, m1, m2, i1);
        top2_update(v[j].w, bi + 3, m1, m2, i1);
    }

    // ---- per-lane exp-sum relative to the lane-local max ----
    // padding values are -inf -> exp underflows to exactly 0, contributing nothing.
    float s = 0.f;
    #pragma unroll
    for (int j = 0; j < 8; ++j) {
        s += __expf(v[j].x - m1) + __expf(v[j].y - m1)
           + __expf(v[j].z - m1) + __expf(v[j].w - m1);
    }

    // ---- single warp reduction: merge (m1, m2, i1, s) online ----
    #pragma unroll
    for (int off = 16; off > 0; off >>= 1) {
        const float om1 = __shfl_down_sync(0xffffffffu, m1, off);
        const float om2 = __shfl_down_sync(0xffffffffu, m2, off);
        const int   oi  = __shfl_down_sync(0xffffffffu, i1, off);
        const float os  = __shfl_down_sync(0xffffffffu, s,  off);
        if (om1 > m1) {
            s  = s * __expf(m1 - om1) + os;
            m2 = fmaxf(m1, om2);
            m1 = om1;
            i1 = oi;
        } else {
            s += os * __expf(om1 - m1);
            m2 = fmaxf(m2, om1);
        }
    }

    // ---- publish per-(row,tensor) stats ----
    __shared__ float s_p0[6], s_p1[6], s_pg[6];
    __shared__ int   s_hit[6];
    if (lane == 0) {
        const float iz = 1.f / s;           // s == sum exp(x - M1)
        s_p0[w]  = iz;                      // top-1 prob
        s_p1[w]  = __expf(m2 - m1) * iz;    // top-2 prob
        s_pg[w]  = __expf(xt - m1) * iz;    // target prob
        s_hit[w] = (i1 == tgt);
    }
    __syncthreads();

    if (tid == 0) {
        float total = 0.f;
        #pragma unroll
        for (int rr = 0; rr < ROWS_PER_BLK; ++rr) {
            const int b = rr * 3;
            const float gt   = s_pg[b] * s_pg[b + 1] * s_pg[b + 2];
            const float top1 = s_p0[b] * s_p0[b + 1] * s_p0[b + 2];
            // smallest of the 8 top-2 products is p1*q1*r1; second-smallest is the
            // min over the three single-promotions (partial-order domination).
            const float c1 = s_p0[b] * s_p1[b + 1] * s_p1[b + 2];
            const float c2 = s_p1[b] * s_p0[b + 1] * s_p1[b + 2];
            const float c3 = s_p1[b] * s_p1[b + 1] * s_p0[b + 2];
            const float second = fminf(c1, fminf(c2, c3));
            const bool cond = s_hit[b] && s_hit[b + 1] && s_hit[b + 2];
            const float pre = cond ? second : top1;
            total += fmaxf(0.f, 1.f - gt + pre);
        }
        g_partial[blockIdx.x] = total;
    }
}

__global__ void __launch_bounds__(1024) rank_reduce_kernel(float* __restrict__ out)
{
    __shared__ float sm[32];
    const int tid = threadIdx.x;
    const float4* p = (const float4*)g_partial;   // 16384 floats = 4096 float4
    float acc = 0.f;
    #pragma unroll
    for (int j = 0; j < 4; ++j) {
        const float4 v = p[tid + j * 1024];
        acc += (v.x + v.y) + (v.z + v.w);
    }
    #pragma unroll
    for (int off = 16; off > 0; off >>= 1)
        acc += __shfl_down_sync(0xffffffffu, acc, off);
    if ((tid & 31) == 0) sm[tid >> 5] = acc;
    __syncthreads();
    if (tid < 32) {
        acc = sm[tid];
        #pragma unroll
        for (int off = 16; off > 0; off >>= 1)
            acc += __shfl_down_sync(0xffffffffu, acc, off);
        if (tid == 0) out[0] = acc * (1.f / (float)NROWS);
    }
}

extern "C" void kernel_launch(void* const* d_in, const int* in_sizes, int n_in,
                              void* d_out, int out_size)
{
    const float* sub = (const float*)d_in[0];
    const float* rel = (const float*)d_in[1];
    const float* obj = (const float*)d_in[2];
    const int*   ts  = (const int*)d_in[3];
    const int*   tr  = (const int*)d_in[4];
    const int*   to  = (const int*)d_in[5];
    float* out = (float*)d_out;

    rank_rows_kernel<<<NBLK, 192>>>(sub, rel, obj, ts, tr, to);
    rank_reduce_kernel<<<1, 1024>>>(out);
}

// round 9
// speedup vs baseline: 1.0010x; 1.0010x over previous
#include <cuda_runtime.h>
#include <math_constants.h>

#define NROWS 32768
#define C_ENT 1000
#define C_REL 500
#define ROWS_PER_BLK 2
#define NBLK (NROWS / ROWS_PER_BLK)   // 16384

// per-block partial loss sums (device global: no allocations allowed)
__device__ float g_partial[NBLK];

__device__ __forceinline__ void top2_update(float x, int i, float& m1, float& m2, int& i1) {
    if (x > m1) { m2 = m1; m1 = x; i1 = i; }
    else if (x > m2) { m2 = x; }
}

__global__ void __launch_bounds__(192) rank_rows_kernel(
    const float* __restrict__ sub, const float* __restrict__ rel, const float* __restrict__ obj,
    const int* __restrict__ t_sub, const int* __restrict__ t_rel, const int* __restrict__ t_obj)
{
    const int tid  = threadIdx.x;
    const int lane = tid & 31;
    const int w    = tid >> 5;          // 0..5
    const int rloc = (w >= 3) ? 1 : 0;  // row within block
    const int t    = w - rloc * 3;      // tensor 0/1/2
    const int r    = blockIdx.x * ROWS_PER_BLK + rloc;

    const float* base;
    const int*   tptr;
    int nvec;
    if (t == 0)      { base = sub + (size_t)r * C_ENT; nvec = C_ENT / 4; tptr = t_sub; }
    else if (t == 1) { base = rel + (size_t)r * C_REL; nvec = C_REL / 4; tptr = t_rel; }
    else             { base = obj + (size_t)r * C_ENT; nvec = C_ENT / 4; tptr = t_obj; }

    // issue the target-index load first so the dependent gather starts ASAP
    int tgt = 0;
    if (lane == 0) tgt = tptr[r];

    // ---- issue all vector loads (MLP = 8 per lane) ----
    float4 v[8];
    #pragma unroll
    for (int j = 0; j < 8; ++j) {
        const int idx = j * 32 + lane;
        v[j] = (idx < nvec) ? ((const float4*)base)[idx]
                            : make_float4(-CUDART_INF_F, -CUDART_INF_F, -CUDART_INF_F, -CUDART_INF_F);
    }

    // dependent target-logit gather (lane 0 only); overlaps with reduction below
    float xt = 0.f;
    if (lane == 0) xt = base[tgt];

    // ---- per-lane top-2 with argmax ----
    // every lane has at least one active vector (j=0: lane < 32 <= nvec), so m1 is finite.
    float m1 = -CUDART_INF_F, m2 = -CUDART_INF_F;
    int   i1 = -1;
    #pragma unroll
    for (int j = 0; j < 8; ++j) {
        const int bi = (j * 32 + lane) * 4;
        top2_update(v[j].x, bi + 0, m1, m2, i1);
        top2_update(v[j].y, bi + 1, m1, m2, i1);
        top2_update(v[j].z, bi + 2, m1, m2, i1);
        top2_update(v[j].w, bi + 3, m1, m2, i1);
    }

    // ---- per-lane exp-sum relative to the lane-local max ----
    // padding values are -inf -> exp underflows to exactly 0, contributing nothing.
    float s = 0.f;
    #pragma unroll
    for (int j = 0; j < 8; ++j) {
        s += __expf(v[j].x - m1) + __expf(v[j].y - m1)
           + __expf(v[j].z - m1) + __expf(v[j].w - m1);
    }

    // ---- single warp reduction: merge (m1, m2, i1, s) online ----
    #pragma unroll
    for (int off = 16; off > 0; off >>= 1) {
        const float om1 = __shfl_down_sync(0xffffffffu, m1, off);
        const float om2 = __shfl_down_sync(0xffffffffu, m2, off);
        const int   oi  = __shfl_down_sync(0xffffffffu, i1, off);
        const float os  = __shfl_down_sync(0xffffffffu, s,  off);
        if (om1 > m1) {
            s  = s * __expf(m1 - om1) + os;
            m2 = fmaxf(m1, om2);
            m1 = om1;
            i1 = oi;
        } else {
            s += os * __expf(om1 - m1);
            m2 = fmaxf(m2, om1);
        }
    }

    // ---- publish per-(row,tensor) stats ----
    __shared__ float s_p0[6], s_p1[6], s_pg[6];
    __shared__ int   s_hit[6];
    if (lane == 0) {
        const float iz = 1.f / s;           // s == sum exp(x - M1)
        s_p0[w]  = iz;                      // top-1 prob
        s_p1[w]  = __expf(m2 - m1) * iz;    // top-2 prob
        s_pg[w]  = __expf(xt - m1) * iz;    // target prob
        s_hit[w] = (i1 == tgt);
    }
    __syncthreads();

    if (tid == 0) {
        float total = 0.f;
        #pragma unroll
        for (int rr = 0; rr < ROWS_PER_BLK; ++rr) {
            const int b = rr * 3;
            const float gt   = s_pg[b] * s_pg[b + 1] * s_pg[b + 2];
            const float top1 = s_p0[b] * s_p0[b + 1] * s_p0[b + 2];
            // smallest of the 8 top-2 products is p1*q1*r1; second-smallest is the
            // min over the three single-promotions (partial-order domination).
            const float c1 = s_p0[b] * s_p1[b + 1] * s_p1[b + 2];
            const float c2 = s_p1[b] * s_p0[b + 1] * s_p1[b + 2];
            const float c3 = s_p1[b] * s_p1[b + 1] * s_p0[b + 2];
            const float second = fminf(c1, fminf(c2, c3));
            const bool cond = s_hit[b] && s_hit[b + 1] && s_hit[b + 2];
            const float pre = cond ? second : top1;
            total += fmaxf(0.f, 1.f - gt + pre);
        }
        g_partial[blockIdx.x] = total;
    }
}

__global__ void __launch_bounds__(1024) rank_reduce_kernel(float* __restrict__ out)
{
    __shared__ float sm[32];
    const int tid = threadIdx.x;
    const float4* p = (const float4*)g_partial;   // 16384 floats = 4096 float4
    float acc = 0.f;
    #pragma unroll
    for (int j = 0; j < 4; ++j) {
        const float4 v = p[tid + j * 1024];
        acc += (v.x + v.y) + (v.z + v.w);
    }
    #pragma unroll
    for (int off = 16; off > 0; off >>= 1)
        acc += __shfl_down_sync(0xffffffffu, acc, off);
    if ((tid & 31) == 0) sm[tid >> 5] = acc;
    __syncthreads();
    if (tid < 32) {
        acc = sm[tid];
        #pragma unroll
        for (int off = 16; off > 0; off >>= 1)
            acc += __shfl_down_sync(0xffffffffu, acc, off);
        if (tid == 0) out[0] = acc * (1.f / (float)NROWS);
    }
}

extern "C" void kernel_launch(void* const* d_in, const int* in_sizes, int n_in,
                              void* d_out, int out_size)
{
    const float* sub = (const float*)d_in[0];
    const float* rel = (const float*)d_in[1];
    const float* obj = (const float*)d_in[2];
    const int*   ts  = (const int*)d_in[3];
    const int*   tr  = (const int*)d_in[4];
    const int*   to  = (const int*)d_in[5];
    float* out = (float*)d_out;

    rank_rows_kernel<<<NBLK, 192>>>(sub, rel, obj, ts, tr, to);
    rank_reduce_kernel<<<1, 1024>>>(out);
}

// round 10
// speedup vs baseline: 1.7695x; 1.7678x over previous
#include <cuda_runtime.h>
#include <math_constants.h>

#define NROWS 32768
#define C_ENT 1000
#define C_REL 500
#define ROWS_PER_BLK 4
#define NBLK (NROWS / ROWS_PER_BLK)   // 8192
#define L2E 1.4426950408889634f

// per-block partial loss sums (device global: no allocations allowed)
__device__ float g_partial[NBLK];

__device__ __forceinline__ float ex2(float x) {
    float y;
    asm("ex2.approx.ftz.f32 %0, %1;" : "=f"(y) : "f"(x));
    return y;
}

__global__ void __launch_bounds__(384) rank_rows_kernel(
    const float* __restrict__ sub, const float* __restrict__ rel, const float* __restrict__ obj,
    const int* __restrict__ t_sub, const int* __restrict__ t_rel, const int* __restrict__ t_obj)
{
    const int tid  = threadIdx.x;
    const int lane = tid & 31;
    const int w    = tid >> 5;          // 0..11
    const int rloc = w / 3;             // row within block, 0..3
    const int t    = w - rloc * 3;      // tensor 0/1/2
    const int r    = blockIdx.x * ROWS_PER_BLK + rloc;

    const float* base;
    const int*   tptr;
    int nvec;
    if (t == 0)      { base = sub + (size_t)r * C_ENT; nvec = C_ENT / 4; tptr = t_sub; }
    else if (t == 1) { base = rel + (size_t)r * C_REL; nvec = C_REL / 4; tptr = t_rel; }
    else             { base = obj + (size_t)r * C_ENT; nvec = C_ENT / 4; tptr = t_obj; }

    // target-index load first so the dependent gather starts ASAP
    int tgt = 0;
    if (lane == 0) tgt = tptr[r];

    // ---- issue all vector loads (MLP = 8 per lane) ----
    float4 v[8];
    #pragma unroll
    for (int j = 0; j < 8; ++j) {
        const int idx = j * 32 + lane;
        v[j] = (idx < nvec) ? ((const float4*)base)[idx]
                            : make_float4(-CUDART_INF_F, -CUDART_INF_F, -CUDART_INF_F, -CUDART_INF_F);
    }

    // dependent target-logit gather (lane 0 only); overlaps with the reduction
    float xt = 0.f;
    if (lane == 0) xt = base[tgt];

    // ---- per-lane branch-free top-2 (3 FMNMX per value, no index) ----
    float m1 = -CUDART_INF_F, m2 = -CUDART_INF_F;
    #pragma unroll
    for (int j = 0; j < 8; ++j) {
        float lo;
        lo = fminf(m1, v[j].x); m1 = fmaxf(m1, v[j].x); m2 = fmaxf(m2, lo);
        lo = fminf(m1, v[j].y); m1 = fmaxf(m1, v[j].y); m2 = fmaxf(m2, lo);
        lo = fminf(m1, v[j].z); m1 = fmaxf(m1, v[j].z); m2 = fmaxf(m2, lo);
        lo = fminf(m1, v[j].w); m1 = fmaxf(m1, v[j].w); m2 = fmaxf(m2, lo);
    }

    // ---- warp-wide (m1, m2) via xor-butterfly: all lanes converge ----
    #pragma unroll
    for (int off = 16; off > 0; off >>= 1) {
        const float om1 = __shfl_xor_sync(0xffffffffu, m1, off);
        const float om2 = __shfl_xor_sync(0xffffffffu, m2, off);
        const float lo  = fminf(m1, om1);
        m1 = fmaxf(m1, om1);
        m2 = fmaxf(fmaxf(m2, om2), lo);
    }

    // ---- exp-sum relative to the warp-global max: FFMA + MUFU + FADD per value ----
    // padding is -inf -> ex2(-inf) = 0 contributes nothing.
    const float c = -m1 * L2E;
    float s0 = 0.f, s1 = 0.f, s2 = 0.f, s3 = 0.f;
    #pragma unroll
    for (int j = 0; j < 8; ++j) {
        s0 += ex2(fmaf(v[j].x, L2E, c));
        s1 += ex2(fmaf(v[j].y, L2E, c));
        s2 += ex2(fmaf(v[j].z, L2E, c));
        s3 += ex2(fmaf(v[j].w, L2E, c));
    }
    float s = (s0 + s1) + (s2 + s3);
    #pragma unroll
    for (int off = 16; off > 0; off >>= 1)
        s += __shfl_xor_sync(0xffffffffu, s, off);

    // ---- publish per-(row,tensor) stats ----
    __shared__ float s_p0[12], s_p1[12], s_pg[12];
    __shared__ int   s_hit[12];
    if (lane == 0) {
        const float iz = 1.f / s;                 // s == sum exp(x - M1)
        s_p0[w]  = iz;                            // top-1 prob
        s_p1[w]  = ex2((m2 - m1) * L2E) * iz;     // top-2 prob
        s_pg[w]  = ex2((xt - m1) * L2E) * iz;     // target prob
        s_hit[w] = (xt == m1);                    // argmax==target <=> x[target]==max
    }
    __syncthreads();

    if (tid == 0) {
        float total = 0.f;
        #pragma unroll
        for (int rr = 0; rr < ROWS_PER_BLK; ++rr) {
            const int b = rr * 3;
            const float gt   = s_pg[b] * s_pg[b + 1] * s_pg[b + 2];
            const float top1 = s_p0[b] * s_p0[b + 1] * s_p0[b + 2];
            // smallest of the 8 top-2 products is p1*q1*r1; second-smallest is the
            // min over the three single-promotions (partial-order domination).
            const float c1 = s_p0[b] * s_p1[b + 1] * s_p1[b + 2];
            const float c2 = s_p1[b] * s_p0[b + 1] * s_p1[b + 2];
            const float c3 = s_p1[b] * s_p1[b + 1] * s_p0[b + 2];
            const float second = fminf(c1, fminf(c2, c3));
            const bool cond = s_hit[b] && s_hit[b + 1] && s_hit[b + 2];
            const float pre = cond ? second : top1;
            total += fmaxf(0.f, 1.f - gt + pre);
        }
        g_partial[blockIdx.x] = total;
    }
}

__global__ void __launch_bounds__(1024) rank_reduce_kernel(float* __restrict__ out)
{
    __shared__ float sm[32];
    const int tid = threadIdx.x;
    const float4* p = (const float4*)g_partial;   // 8192 floats = 2048 float4
    float acc = 0.f;
    #pragma unroll
    for (int j = 0; j < 2; ++j) {
        const float4 v = p[tid + j * 1024];
        acc += (v.x + v.y) + (v.z + v.w);
    }
    #pragma unroll
    for (int off = 16; off > 0; off >>= 1)
        acc += __shfl_down_sync(0xffffffffu, acc, off);
    if ((tid & 31) == 0) sm[tid >> 5] = acc;
    __syncthreads();
    if (tid < 32) {
        acc = sm[tid];
        #pragma unroll
        for (int off = 16; off > 0; off >>= 1)
            acc += __shfl_down_sync(0xffffffffu, acc, off);
        if (tid == 0) out[0] = acc * (1.f / (float)NROWS);
    }
}

extern "C" void kernel_launch(void* const* d_in, const int* in_sizes, int n_in,
                              void* d_out, int out_size)
{
    const float* sub = (const float*)d_in[0];
    const float* rel = (const float*)d_in[1];
    const float* obj = (const float*)d_in[2];
    const int*   ts  = (const int*)d_in[3];
    const int*   tr  = (const int*)d_in[4];
    const int*   to  = (const int*)d_in[5];
    float* out = (float*)d_out;

    rank_rows_kernel<<<NBLK, 384>>>(sub, rel, obj, ts, tr, to);
    rank_reduce_kernel<<<1, 1024>>>(out);
}